// round 7
// baseline (speedup 1.0000x reference)
#include <cuda_runtime.h>
#include <math.h>

#define HH 96
#define WW 96
#define HWc 9216         // 96*96
#define BB 4
#define NN 36864         // BB*HWc

// ---------------- scratch (static device allocations; no cudaMalloc) ----------
__device__ float g_col[169869312];   // max 9*512 x 36864  (layer 3)  ~680 MB
__device__ float g_wA[1179648];      // max O*9*C = 256*4608
__device__ float g_y1[2359296];      // 4*64*9216
__device__ float g_y2[18874368];     // 4*512*9216
__device__ float g_py[331776];       // 4*9*9216
__device__ float g_px[331776];
__device__ float g_mask[331776];

// ---------------- 1) offset conv: om = conv3x3(x, ow) + ob → py/px/mask -------
// block = 128 threads = 16x8 pixel tile; grid = (6, 12, B)
template<int CB>
__global__ void offset_conv_kernel(const float* __restrict__ x,
                                   const float* __restrict__ ow,
                                   const float* __restrict__ ob, int C)
{
    __shared__ float ws[CB * 9 * 27];
    const int tid = threadIdx.x;
    const int tx = tid & 15, ty = tid >> 4;
    const int w0 = blockIdx.x * 16 + tx;
    const int h0 = blockIdx.y * 8 + ty;
    const int b  = blockIdx.z;

    float acc[27];
#pragma unroll
    for (int i = 0; i < 27; i++) acc[i] = 0.f;

    for (int c0 = 0; c0 < C; c0 += CB) {
        __syncthreads();
        for (int i = tid; i < CB * 9 * 27; i += 128) {
            int oc  = i % 27;
            int r   = i / 27;
            int tap = r % 9;
            int cc  = r / 9;
            ws[i] = ow[((size_t)oc * C + c0 + cc) * 9 + tap];
        }
        __syncthreads();

        for (int cc = 0; cc < CB; cc++) {
            const float* xp = x + ((size_t)b * C + c0 + cc) * HWc;
            float xv[9];
#pragma unroll
            for (int dy = 0; dy < 3; dy++)
#pragma unroll
                for (int dx = 0; dx < 3; dx++) {
                    int yy = h0 + dy - 1, xx = w0 + dx - 1;
                    bool v = (yy >= 0) & (yy < HH) & (xx >= 0) & (xx < WW);
                    xv[dy * 3 + dx] = v ? xp[yy * WW + xx] : 0.f;
                }
#pragma unroll
            for (int tap = 0; tap < 9; tap++) {
                const float* wr = &ws[(cc * 9 + tap) * 27];
                float xvv = xv[tap];
#pragma unroll
                for (int oc = 0; oc < 27; oc++) acc[oc] += xvv * wr[oc];
            }
        }
    }

#pragma unroll
    for (int i = 0; i < 27; i++) acc[i] += ob[i];

    const int pix = h0 * WW + w0;
#pragma unroll
    for (int k = 0; k < 9; k++) {
        float oy = acc[2 * k];
        float ox = acc[2 * k + 1];
        float m  = 1.f / (1.f + __expf(-acc[18 + k]));
        int ky = k / 3, kx = k % 3;
        int idx = (b * 9 + k) * HWc + pix;
        g_py[idx]   = (float)(h0 + ky - 1) + oy;
        g_px[idx]   = (float)(w0 + kx - 1) + ox;
        g_mask[idx] = m;
    }
}

// ---------------- 2) deformable im2col gather → g_col[9C, NN] ----------------
__global__ void gather_kernel(const float* __restrict__ x, int C)
{
    int idx = blockIdx.x * blockDim.x + threadIdx.x;  // over BB*9*HWc
    if (idx >= BB * 9 * HWc) return;
    int hw = idx % HWc;
    int bk = idx / HWc;
    int k  = bk % 9;
    int b  = bk / 9;

    float pyv = g_py[idx], pxv = g_px[idx], m = g_mask[idx];
    float y0f = floorf(pyv), x0f = floorf(pxv);
    float wy = pyv - y0f, wx = pxv - x0f;
    int y0 = (int)y0f, x0 = (int)x0f;
    int y1 = y0 + 1, x1 = x0 + 1;
    float vy0 = (y0 >= 0 && y0 < HH) ? 1.f : 0.f;
    float vy1 = (y1 >= 0 && y1 < HH) ? 1.f : 0.f;
    float vx0 = (x0 >= 0 && x0 < WW) ? 1.f : 0.f;
    float vx1 = (x1 >= 0 && x1 < WW) ? 1.f : 0.f;
    float w00 = (1.f - wy) * (1.f - wx) * m * vy0 * vx0;
    float w01 = (1.f - wy) * wx         * m * vy0 * vx1;
    float w10 = wy         * (1.f - wx) * m * vy1 * vx0;
    float w11 = wy         * wx         * m * vy1 * vx1;

    int cy0 = min(max(y0, 0), HH - 1), cy1 = min(max(y1, 0), HH - 1);
    int cx0 = min(max(x0, 0), WW - 1), cx1 = min(max(x1, 0), WW - 1);
    int o00 = cy0 * WW + cx0, o01 = cy0 * WW + cx1;
    int o10 = cy1 * WW + cx0, o11 = cy1 * WW + cx1;

    const float* base = x + (size_t)b * C * HWc;
    size_t outIdx = (size_t)k * C * NN + (size_t)b * HWc + hw;
#pragma unroll 4
    for (int c = 0; c < C; c++) {
        const float* p = base + (size_t)c * HWc;
        float v = w00 * p[o00] + w01 * p[o01] + w10 * p[o10] + w11 * p[o11];
        g_col[outIdx] = v;
        outIdx += NN;
    }
}

// ---------------- 3a) weight repack: wA[o][k*C + c] = w[o][c][k] -------------
__global__ void repack_w_kernel(const float* __restrict__ w, int O, int C)
{
    int idx = blockIdx.x * blockDim.x + threadIdx.x;
    if (idx >= O * C * 9) return;
    int tap = idx % 9;
    int c   = (idx / 9) % C;
    int o   = idx / (9 * C);
    g_wA[(size_t)o * 9 * C + tap * C + c] = w[idx];
}

// ---------------- 3b) SGEMM: out[o][n] = sum_kc wA[o][kc]*col[kc][n] ---------
// BN=128, BK=8, TM=TN=8; BM templated (64 or 128). N=36864 (divides 128),
// K = 9*C (divides 8), M = O (divides BM). Epilogue adds bias and scatters
// into [B, O, H, W] layout (n-tiles never straddle batch: HWc % 128 == 0).
template<int BM>
__global__ void sgemm_kernel(int K, const float* __restrict__ bias,
                             float* __restrict__ out, int O)
{
    const int BN = 128, BK = 8, TM = 8, TN = 8;
    const int THREADS = (BM / TM) * (BN / TN);
    __shared__ float As[BK * BM];
    __shared__ float Bs[BK * BN];
    const int tid  = threadIdx.x;
    const int tcol = tid % (BN / TN);
    const int trow = tid / (BN / TN);

    const float* A  = g_wA + (size_t)blockIdx.y * BM * K;
    const float* Bp = g_col + blockIdx.x * BN;

    float acc[TM][TN];
#pragma unroll
    for (int i = 0; i < TM; i++)
#pragma unroll
        for (int j = 0; j < TN; j++) acc[i][j] = 0.f;

    const int aRow = tid / 2;
    const int aCol = (tid & 1) * 4;
    const int aStride = THREADS / 2;
    const int bRow = tid / 32;
    const int bCol = (tid & 31) * 4;
    const int bStride = THREADS / 32;

    for (int k0 = 0; k0 < K; k0 += BK) {
#pragma unroll
        for (int r = aRow; r < BM; r += aStride) {
            float4 v = *(const float4*)(A + (size_t)r * K + k0 + aCol);
            As[(aCol + 0) * BM + r] = v.x;
            As[(aCol + 1) * BM + r] = v.y;
            As[(aCol + 2) * BM + r] = v.z;
            As[(aCol + 3) * BM + r] = v.w;
        }
#pragma unroll
        for (int r = bRow; r < BK; r += bStride) {
            *(float4*)(&Bs[r * BN + bCol]) =
                *(const float4*)(Bp + (size_t)(k0 + r) * NN + bCol);
        }
        __syncthreads();
#pragma unroll
        for (int kk = 0; kk < BK; kk++) {
            float regM[TM], regN[TN];
#pragma unroll
            for (int i = 0; i < TM; i++) regM[i] = As[kk * BM + trow * TM + i];
#pragma unroll
            for (int j = 0; j < TN; j++) regN[j] = Bs[kk * BN + tcol * TN + j];
#pragma unroll
            for (int i = 0; i < TM; i++)
#pragma unroll
                for (int j = 0; j < TN; j++)
                    acc[i][j] += regM[i] * regN[j];
        }
        __syncthreads();
    }

    const int nBase = blockIdx.x * BN + tcol * TN;
    const int b   = nBase / HWc;
    const int hw0 = nBase % HWc;
    const int mBase = blockIdx.y * BM + trow * TM;
#pragma unroll
    for (int i = 0; i < TM; i++) {
        int o = mBase + i;
        float bv = bias[o];
        float* op = out + ((size_t)b * O + o) * HWc + hw0;
#pragma unroll
        for (int j = 0; j < TN; j += 4) {
            float4 v;
            v.x = acc[i][j + 0] + bv;
            v.y = acc[i][j + 1] + bv;
            v.z = acc[i][j + 2] + bv;
            v.w = acc[i][j + 3] + bv;
            *(float4*)(op + j) = v;
        }
    }
}

// ---------------- host-side layer driver -------------------------------------
static void run_layer(const float* in, int C,
                      const float* ow, const float* obias,
                      const float* w, const float* bias, int O, float* out)
{
    dim3 gOff(WW / 16, HH / 8, BB);
    offset_conv_kernel<16><<<gOff, 128>>>(in, ow, obias, C);

    int nG = BB * 9 * HWc;
    gather_kernel<<<(nG + 255) / 256, 256>>>(in, C);

    int nW = O * C * 9;
    repack_w_kernel<<<(nW + 255) / 256, 256>>>(w, O, C);

    int K = 9 * C;
    if (O >= 128) {
        dim3 grid(NN / 128, O / 128);
        sgemm_kernel<128><<<grid, 256>>>(K, bias, out, O);
    } else {
        dim3 grid(NN / 128, O / 64);
        sgemm_kernel<64><<<grid, 128>>>(K, bias, out, O);
    }
}

extern "C" void kernel_launch(void* const* d_in, const int* in_sizes, int n_in,
                              void* d_out, int out_size)
{
    const float* x   = (const float*)d_in[0];
    const float* ow1 = (const float*)d_in[1];
    const float* ob1 = (const float*)d_in[2];
    const float* w1  = (const float*)d_in[3];
    const float* b1  = (const float*)d_in[4];
    const float* ow2 = (const float*)d_in[5];
    const float* ob2 = (const float*)d_in[6];
    const float* w2  = (const float*)d_in[7];
    const float* b2  = (const float*)d_in[8];
    const float* ow3 = (const float*)d_in[9];
    const float* ob3 = (const float*)d_in[10];
    const float* w3  = (const float*)d_in[11];
    const float* b3  = (const float*)d_in[12];
    float* out = (float*)d_out;

    float *y1 = nullptr, *y2 = nullptr;
    cudaGetSymbolAddress((void**)&y1, g_y1);
    cudaGetSymbolAddress((void**)&y2, g_y2);

    run_layer(x,   64, ow1, ob1, w1, b1,  64, y1);
    run_layer(y1,  64, ow2, ob2, w2, b2, 512, y2);
    run_layer(y2, 512, ow3, ob3, w3, b3, 256, out);
}

// round 9
// speedup vs baseline: 1.0564x; 1.0564x over previous
#include <cuda_runtime.h>
#include <cuda_bf16.h>
#include <math.h>
#include <stdint.h>

#define HH 96
#define WW 96
#define HWc 9216         // 96*96
#define BB 4
#define NN 36864         // BB*HWc

// ---------------- scratch (static device arrays; no cudaMalloc) --------------
__device__ uint16_t g_colh[169869312];   // bf16 hi: [NN][K] K-major (K<=4608)
__device__ uint16_t g_coll[169869312];   // bf16 lo
__device__ uint16_t g_wAh[1179648];      // bf16 hi: [Opad][K] K-major
__device__ uint16_t g_wAl[1179648];      // bf16 lo
__device__ float    g_y1[2359296];       // 4*64*9216
__device__ float    g_y2[18874368];      // 4*512*9216
__device__ float    g_py[331776];        // 4*9*9216
__device__ float    g_px[331776];
__device__ float    g_mask[331776];

// ---------------- PTX helpers (generic compute_103-legal only) ---------------
__device__ __forceinline__ uint32_t smem_u32(const void* p) {
    uint32_t a;
    asm("{ .reg .u64 t; cvta.to.shared.u64 t, %1; cvt.u32.u64 %0, t; }"
        : "=r"(a) : "l"(p));
    return a;
}

__device__ __forceinline__ void cp16(uint32_t saddr, const void* g) {
    asm volatile("cp.async.cg.shared.global [%0], [%1], 16;"
                 :: "r"(saddr), "l"(g) : "memory");
}

__device__ __forceinline__ void ldsm4(uint32_t* r, uint32_t addr) {
    asm volatile("ldmatrix.sync.aligned.m8n8.x4.shared.b16 {%0,%1,%2,%3}, [%4];"
                 : "=r"(r[0]), "=r"(r[1]), "=r"(r[2]), "=r"(r[3]) : "r"(addr));
}

__device__ __forceinline__ void mma_bf16(float* d, const uint32_t* a,
                                         const uint32_t* b) {
    asm volatile(
        "mma.sync.aligned.m16n8k16.row.col.f32.bf16.bf16.f32 "
        "{%0,%1,%2,%3}, {%4,%5,%6,%7}, {%8,%9}, {%0,%1,%2,%3};"
        : "+f"(d[0]), "+f"(d[1]), "+f"(d[2]), "+f"(d[3])
        : "r"(a[0]), "r"(a[1]), "r"(a[2]), "r"(a[3]), "r"(b[0]), "r"(b[1]));
}

// ---------------- 1) offset conv: om = conv3x3(x, ow) + ob -> py/px/mask -----
template<int CB>
__global__ void offset_conv_kernel(const float* __restrict__ x,
                                   const float* __restrict__ ow,
                                   const float* __restrict__ ob, int C)
{
    __shared__ float ws[CB * 9 * 27];
    const int tid = threadIdx.x;
    const int tx = tid & 15, ty = tid >> 4;
    const int w0 = blockIdx.x * 16 + tx;
    const int h0 = blockIdx.y * 8 + ty;
    const int b  = blockIdx.z;

    float acc[27];
#pragma unroll
    for (int i = 0; i < 27; i++) acc[i] = 0.f;

    for (int c0 = 0; c0 < C; c0 += CB) {
        __syncthreads();
        for (int i = tid; i < CB * 9 * 27; i += 128) {
            int oc  = i % 27;
            int r   = i / 27;
            int tap = r % 9;
            int cc  = r / 9;
            ws[i] = ow[((size_t)oc * C + c0 + cc) * 9 + tap];
        }
        __syncthreads();

        for (int cc = 0; cc < CB; cc++) {
            const float* xp = x + ((size_t)b * C + c0 + cc) * HWc;
            float xv[9];
#pragma unroll
            for (int dy = 0; dy < 3; dy++)
#pragma unroll
                for (int dx = 0; dx < 3; dx++) {
                    int yy = h0 + dy - 1, xx = w0 + dx - 1;
                    bool v = (yy >= 0) & (yy < HH) & (xx >= 0) & (xx < WW);
                    xv[dy * 3 + dx] = v ? xp[yy * WW + xx] : 0.f;
                }
#pragma unroll
            for (int tap = 0; tap < 9; tap++) {
                const float* wr = &ws[(cc * 9 + tap) * 27];
                float xvv = xv[tap];
#pragma unroll
                for (int oc = 0; oc < 27; oc++) acc[oc] += xvv * wr[oc];
            }
        }
    }

#pragma unroll
    for (int i = 0; i < 27; i++) acc[i] += ob[i];

    const int pix = h0 * WW + w0;
#pragma unroll
    for (int k = 0; k < 9; k++) {
        float oy = acc[2 * k];
        float ox = acc[2 * k + 1];
        float m  = 1.f / (1.f + __expf(-acc[18 + k]));
        int ky = k / 3, kx = k % 3;
        int idx = (b * 9 + k) * HWc + pix;
        g_py[idx]   = (float)(h0 + ky - 1) + oy;
        g_px[idx]   = (float)(w0 + kx - 1) + ox;
        g_mask[idx] = m;
    }
}

// ---------------- 2) deformable im2col gather -> colh/coll [N][K] K-major ----
__global__ void gather_kernel(const float* __restrict__ x, int C)
{
    int idx = blockIdx.x * blockDim.x + threadIdx.x;  // over BB*9*HWc
    if (idx >= BB * 9 * HWc) return;
    int hw = idx % HWc;
    int bk = idx / HWc;
    int k  = bk % 9;
    int b  = bk / 9;
    const int K = 9 * C;
    const size_t n = (size_t)b * HWc + hw;

    float pyv = g_py[idx], pxv = g_px[idx], m = g_mask[idx];
    float y0f = floorf(pyv), x0f = floorf(pxv);
    float wy = pyv - y0f, wx = pxv - x0f;
    int y0 = (int)y0f, x0 = (int)x0f;
    int y1 = y0 + 1, x1 = x0 + 1;
    float vy0 = (y0 >= 0 && y0 < HH) ? 1.f : 0.f;
    float vy1 = (y1 >= 0 && y1 < HH) ? 1.f : 0.f;
    float vx0 = (x0 >= 0 && x0 < WW) ? 1.f : 0.f;
    float vx1 = (x1 >= 0 && x1 < WW) ? 1.f : 0.f;
    float w00 = (1.f - wy) * (1.f - wx) * m * vy0 * vx0;
    float w01 = (1.f - wy) * wx         * m * vy0 * vx1;
    float w10 = wy         * (1.f - wx) * m * vy1 * vx0;
    float w11 = wy         * wx         * m * vy1 * vx1;

    int cy0 = min(max(y0, 0), HH - 1), cy1 = min(max(y1, 0), HH - 1);
    int cx0 = min(max(x0, 0), WW - 1), cx1 = min(max(x1, 0), WW - 1);
    int o00 = cy0 * WW + cx0, o01 = cy0 * WW + cx1;
    int o10 = cy1 * WW + cx0, o11 = cy1 * WW + cx1;

    const float* base = x + (size_t)b * C * HWc;
    size_t outBase = n * (size_t)K + (size_t)k * C;

    for (int c = 0; c < C; c += 2) {
        const float* p0 = base + (size_t)c * HWc;
        const float* p1 = p0 + HWc;
        float v0 = w00 * p0[o00] + w01 * p0[o01] + w10 * p0[o10] + w11 * p0[o11];
        float v1 = w00 * p1[o00] + w01 * p1[o01] + w10 * p1[o10] + w11 * p1[o11];
        __nv_bfloat16 h0 = __float2bfloat16(v0);
        __nv_bfloat16 h1 = __float2bfloat16(v1);
        __nv_bfloat16 l0 = __float2bfloat16(v0 - __bfloat162float(h0));
        __nv_bfloat16 l1 = __float2bfloat16(v1 - __bfloat162float(h1));
        uint32_t hp = (uint32_t)__bfloat16_as_ushort(h0) |
                      ((uint32_t)__bfloat16_as_ushort(h1) << 16);
        uint32_t lp = (uint32_t)__bfloat16_as_ushort(l0) |
                      ((uint32_t)__bfloat16_as_ushort(l1) << 16);
        *reinterpret_cast<uint32_t*>(&g_colh[outBase + c]) = hp;
        *reinterpret_cast<uint32_t*>(&g_coll[outBase + c]) = lp;
    }
}

// ---------------- 3a) weight repack+split: wA[o][tap*C+c] = w[o][c][tap] -----
__global__ void repack_split_kernel(const float* __restrict__ w,
                                    int O, int Opad, int C)
{
    int K = 9 * C;
    int idx = blockIdx.x * blockDim.x + threadIdx.x;
    if (idx >= Opad * K) return;
    int kk = idx % K;
    int o  = idx / K;
    int tap = kk / C;
    int c   = kk % C;
    float v = (o < O) ? w[((size_t)o * C + c) * 9 + tap] : 0.f;
    __nv_bfloat16 h = __float2bfloat16(v);
    __nv_bfloat16 l = __float2bfloat16(v - __bfloat162float(h));
    g_wAh[idx] = __bfloat16_as_ushort(h);
    g_wAl[idx] = __bfloat16_as_ushort(l);
}

// ---------------- 3b) bf16-split HMMA GEMM -----------------------------------
// D[O,N] = wA · col^T.  CTA tile 128x128, 8 warps (4M x 2N), warp tile 32x64.
// K-chunk = 32 bf16.  SMEM rows padded to 80B (conflict-free ldmatrix).
// Split: acc += Ah·Bh + Ah·Bl + Al·Bh  (fp32 accumulate in registers).
#define KC 32
#define RS 80                    // padded SMEM row stride (bytes)
#define TSZ (128 * RS)           // 10240 bytes per tile
#define GSMEM_TOTAL (8 * TSZ)    // 4 arrays x 2 buffers = 81920 bytes

__global__ void __launch_bounds__(256)
dcn_gemm_kernel(const float* __restrict__ bias, float* __restrict__ out,
                int K, int O)
{
    extern __shared__ char smem[];
    const uint32_t sb = smem_u32(smem);
    const int tid = threadIdx.x, lid = tid & 31, wid = tid >> 5;
    const int warpM = wid & 3;        // 0..3 -> 32-row slices
    const int warpN = wid >> 2;       // 0..1 -> 64-col slices
    const int m0 = blockIdx.y * 128;
    const int n0 = blockIdx.x * 128;

    float acc[2][8][4];
#pragma unroll
    for (int mt = 0; mt < 2; mt++)
#pragma unroll
        for (int nt = 0; nt < 8; nt++)
#pragma unroll
            for (int r = 0; r < 4; r++) acc[mt][nt][r] = 0.f;

    const char* pAh = (const char*)g_wAh  + (size_t)m0 * K * 2;
    const char* pAl = (const char*)g_wAl  + (size_t)m0 * K * 2;
    const char* pBh = (const char*)g_colh + (size_t)n0 * K * 2;
    const char* pBl = (const char*)g_coll + (size_t)n0 * K * 2;

    auto load_chunk = [&](int c, int buf) {
        size_t kb = (size_t)c * (KC * 2);
        uint32_t sbase = sb + (uint32_t)buf * 4 * TSZ;
#pragma unroll
        for (int i = 0; i < 8; i++) {
            int s   = tid + i * 256;       // 0..2047
            int arr = s >> 9;              // 0..3
            int rs  = s & 511;
            int row = rs >> 2;             // 0..127
            int seg = rs & 3;              // 0..3 (16B segments of 64B row)
            size_t go = (size_t)row * K * 2 + kb + (size_t)seg * 16;
            const char* g = (arr == 0) ? pAh + go :
                            (arr == 1) ? pAl + go :
                            (arr == 2) ? pBh + go : pBl + go;
            cp16(sbase + arr * TSZ + row * RS + seg * 16, g);
        }
    };

    auto compute_chunk = [&](int buf) {
        uint32_t base = sb + (uint32_t)buf * 4 * TSZ;
        const uint32_t lrow = lid & 15;
        const uint32_t lcol = (lid >> 4) * 16;
#pragma unroll
        for (int ks = 0; ks < 2; ks++) {
            const uint32_t kb = ks * 32;   // bytes: 16 bf16 per k16 step
            uint32_t ah[2][4], al[2][4], bb[8][2];
#pragma unroll
            for (int mt = 0; mt < 2; mt++) {
                uint32_t r = warpM * 32 + mt * 16 + lrow;
                ldsm4(ah[mt], base + 0 * TSZ + r * RS + kb + lcol);
                ldsm4(al[mt], base + 1 * TSZ + r * RS + kb + lcol);
            }
            // Bh fragments
#pragma unroll
            for (int np = 0; np < 4; np++) {
                uint32_t t[4];
                uint32_t r = warpN * 64 + np * 16 + lrow;
                ldsm4(t, base + 2 * TSZ + r * RS + kb + lcol);
                bb[2 * np][0] = t[0]; bb[2 * np][1] = t[2];
                bb[2 * np + 1][0] = t[1]; bb[2 * np + 1][1] = t[3];
            }
#pragma unroll
            for (int mt = 0; mt < 2; mt++)
#pragma unroll
                for (int nt = 0; nt < 8; nt++)
                    mma_bf16(acc[mt][nt], ah[mt], bb[nt]);   // Ah*Bh
#pragma unroll
            for (int mt = 0; mt < 2; mt++)
#pragma unroll
                for (int nt = 0; nt < 8; nt++)
                    mma_bf16(acc[mt][nt], al[mt], bb[nt]);   // Al*Bh
            // Bl fragments (reuse bb regs)
#pragma unroll
            for (int np = 0; np < 4; np++) {
                uint32_t t[4];
                uint32_t r = warpN * 64 + np * 16 + lrow;
                ldsm4(t, base + 3 * TSZ + r * RS + kb + lcol);
                bb[2 * np][0] = t[0]; bb[2 * np][1] = t[2];
                bb[2 * np + 1][0] = t[1]; bb[2 * np + 1][1] = t[3];
            }
#pragma unroll
            for (int mt = 0; mt < 2; mt++)
#pragma unroll
                for (int nt = 0; nt < 8; nt++)
                    mma_bf16(acc[mt][nt], ah[mt], bb[nt]);   // Ah*Bl
        }
    };

    const int nCh = K / KC;
    load_chunk(0, 0);
    asm volatile("cp.async.commit_group;" ::: "memory");

    for (int c = 0; c < nCh; c++) {
        int buf = c & 1;
        if (c + 1 < nCh) {
            load_chunk(c + 1, buf ^ 1);
            asm volatile("cp.async.commit_group;" ::: "memory");
            asm volatile("cp.async.wait_group 1;" ::: "memory");
        } else {
            asm volatile("cp.async.wait_group 0;" ::: "memory");
        }
        __syncthreads();
        compute_chunk(buf);
        __syncthreads();
    }

    // ---- epilogue: +bias, scatter into [B, O, H, W] -------------------------
    const int b   = n0 / HWc;
    const int hw0 = n0 % HWc;
    const int grp = lid >> 2;
    const int tig = lid & 3;
#pragma unroll
    for (int mt = 0; mt < 2; mt++) {
        int oA = m0 + warpM * 32 + mt * 16 + grp;
        int oB = oA + 8;
#pragma unroll
        for (int nt = 0; nt < 8; nt++) {
            int cn = warpN * 64 + nt * 8 + tig * 2;
            if (oA < O) {
                float bv = bias[oA];
                float2 v = make_float2(acc[mt][nt][0] + bv, acc[mt][nt][1] + bv);
                *(float2*)(out + ((size_t)b * O + oA) * HWc + hw0 + cn) = v;
            }
            if (oB < O) {
                float bv = bias[oB];
                float2 v = make_float2(acc[mt][nt][2] + bv, acc[mt][nt][3] + bv);
                *(float2*)(out + ((size_t)b * O + oB) * HWc + hw0 + cn) = v;
            }
        }
    }
}

// ---------------- host-side layer driver -------------------------------------
static void run_layer(const float* in, int C,
                      const float* ow, const float* obias,
                      const float* w, const float* bias,
                      int O, int Opad, float* out)
{
    dim3 gOff(WW / 16, HH / 8, BB);
    offset_conv_kernel<16><<<gOff, 128>>>(in, ow, obias, C);

    int nG = BB * 9 * HWc;
    gather_kernel<<<(nG + 255) / 256, 256>>>(in, C);

    int K = 9 * C;
    int nW = Opad * K;
    repack_split_kernel<<<(nW + 255) / 256, 256>>>(w, O, Opad, C);

    dim3 grid(NN / 128, Opad / 128);
    dcn_gemm_kernel<<<grid, 256, GSMEM_TOTAL>>>(bias, out, K, O);
}

extern "C" void kernel_launch(void* const* d_in, const int* in_sizes, int n_in,
                              void* d_out, int out_size)
{
    const float* x   = (const float*)d_in[0];
    const float* ow1 = (const float*)d_in[1];
    const float* ob1 = (const float*)d_in[2];
    const float* w1  = (const float*)d_in[3];
    const float* b1  = (const float*)d_in[4];
    const float* ow2 = (const float*)d_in[5];
    const float* ob2 = (const float*)d_in[6];
    const float* w2  = (const float*)d_in[7];
    const float* b2  = (const float*)d_in[8];
    const float* ow3 = (const float*)d_in[9];
    const float* ob3 = (const float*)d_in[10];
    const float* w3  = (const float*)d_in[11];
    const float* b3  = (const float*)d_in[12];
    float* out = (float*)d_out;

    cudaFuncSetAttribute(dcn_gemm_kernel,
                         cudaFuncAttributeMaxDynamicSharedMemorySize, GSMEM_TOTAL);

    float *y1 = nullptr, *y2 = nullptr;
    cudaGetSymbolAddress((void**)&y1, g_y1);
    cudaGetSymbolAddress((void**)&y2, g_y2);

    run_layer(x,   64, ow1, ob1, w1, b1,  64, 128, y1);
    run_layer(y1,  64, ow2, ob2, w2, b2, 512, 512, y2);
    run_layer(y2, 512, ow3, ob3, w3, b3, 256, 256, out);
}

// round 10
// speedup vs baseline: 1.9868x; 1.8806x over previous
#include <cuda_runtime.h>
#include <cuda_fp16.h>
#include <math.h>
#include <stdint.h>

#define HH 96
#define WW 96
#define HWc 9216         // 96*96
#define BB 4
#define NN 36864         // BB*HWc

// ---------------- scratch (static device arrays; no cudaMalloc) --------------
__device__ uint16_t g_col[169869312];    // f16: [NN][K] K-major (K<=4608), 340MB
__device__ uint16_t g_wAh[1179648];      // f16 hi: [Opad][K] K-major
__device__ uint16_t g_wAl[1179648];      // f16 lo
__device__ float    g_y1[2359296];       // 4*64*9216
__device__ float    g_y2[18874368];      // 4*512*9216
__device__ float    g_py[331776];        // 4*9*9216
__device__ float    g_px[331776];
__device__ float    g_mask[331776];

// ---------------- PTX helpers (generic compute_103-legal only) ---------------
__device__ __forceinline__ uint32_t smem_u32(const void* p) {
    uint32_t a;
    asm("{ .reg .u64 t; cvta.to.shared.u64 t, %1; cvt.u32.u64 %0, t; }"
        : "=r"(a) : "l"(p));
    return a;
}

__device__ __forceinline__ void cp16(uint32_t saddr, const void* g) {
    asm volatile("cp.async.cg.shared.global [%0], [%1], 16;"
                 :: "r"(saddr), "l"(g) : "memory");
}

__device__ __forceinline__ void ldsm4(uint32_t* r, uint32_t addr) {
    asm volatile("ldmatrix.sync.aligned.m8n8.x4.shared.b16 {%0,%1,%2,%3}, [%4];"
                 : "=r"(r[0]), "=r"(r[1]), "=r"(r[2]), "=r"(r[3]) : "r"(addr));
}

__device__ __forceinline__ void mma_f16(float* d, const uint32_t* a,
                                        const uint32_t* b) {
    asm volatile(
        "mma.sync.aligned.m16n8k16.row.col.f32.f16.f16.f32 "
        "{%0,%1,%2,%3}, {%4,%5,%6,%7}, {%8,%9}, {%0,%1,%2,%3};"
        : "+f"(d[0]), "+f"(d[1]), "+f"(d[2]), "+f"(d[3])
        : "r"(a[0]), "r"(a[1]), "r"(a[2]), "r"(a[3]), "r"(b[0]), "r"(b[1]));
}

// ---------------- 1) offset conv: om = conv3x3(x, ow) + ob -> py/px/mask -----
// 256 threads = 32x8 pixel tile; ws rows padded to 28 floats for float4 LDS.
template<int CB>
__global__ void offset_conv_kernel(const float* __restrict__ x,
                                   const float* __restrict__ ow,
                                   const float* __restrict__ ob, int C)
{
    __shared__ float ws[CB * 9 * 28];
    const int tid = threadIdx.x;
    const int tx = tid & 31, ty = tid >> 5;
    const int w0 = blockIdx.x * 32 + tx;
    const int h0 = blockIdx.y * 8 + ty;
    const int b  = blockIdx.z;

    float acc[28];
#pragma unroll
    for (int i = 0; i < 28; i++) acc[i] = 0.f;

    for (int c0 = 0; c0 < C; c0 += CB) {
        __syncthreads();
        for (int i = tid; i < CB * 9 * 28; i += 256) {
            int oc  = i % 28;
            int r   = i / 28;
            int tap = r % 9;
            int cc  = r / 9;
            ws[i] = (oc < 27) ? ow[((size_t)oc * C + c0 + cc) * 9 + tap] : 0.f;
        }
        __syncthreads();

        for (int cc = 0; cc < CB; cc++) {
            const float* xp = x + ((size_t)b * C + c0 + cc) * HWc;
            float xv[9];
#pragma unroll
            for (int dy = 0; dy < 3; dy++)
#pragma unroll
                for (int dx = 0; dx < 3; dx++) {
                    int yy = h0 + dy - 1, xx = w0 + dx - 1;
                    bool v = (yy >= 0) & (yy < HH) & (xx >= 0) & (xx < WW);
                    xv[dy * 3 + dx] = v ? xp[yy * WW + xx] : 0.f;
                }
#pragma unroll
            for (int tap = 0; tap < 9; tap++) {
                const float* wr = &ws[(cc * 9 + tap) * 28];
                float xvv = xv[tap];
#pragma unroll
                for (int q = 0; q < 7; q++) {
                    float4 wv = *(const float4*)(wr + q * 4);
                    acc[q * 4 + 0] += xvv * wv.x;
                    acc[q * 4 + 1] += xvv * wv.y;
                    acc[q * 4 + 2] += xvv * wv.z;
                    acc[q * 4 + 3] += xvv * wv.w;
                }
            }
        }
    }

#pragma unroll
    for (int i = 0; i < 27; i++) acc[i] += ob[i];

    const int pix = h0 * WW + w0;
#pragma unroll
    for (int k = 0; k < 9; k++) {
        float oy = acc[2 * k];
        float ox = acc[2 * k + 1];
        float m  = 1.f / (1.f + __expf(-acc[18 + k]));
        int ky = k / 3, kx = k % 3;
        int idx = (b * 9 + k) * HWc + pix;
        g_py[idx]   = (float)(h0 + ky - 1) + oy;
        g_px[idx]   = (float)(w0 + kx - 1) + ox;
        g_mask[idx] = m;
    }
}

// ---------------- 2) deformable im2col gather -> g_col (f16, [N][K]) ---------
__global__ void gather_kernel(const float* __restrict__ x, int C)
{
    int idx = blockIdx.x * blockDim.x + threadIdx.x;  // over BB*9*HWc
    if (idx >= BB * 9 * HWc) return;
    int hw = idx % HWc;
    int bk = idx / HWc;
    int k  = bk % 9;
    int b  = bk / 9;
    const int K = 9 * C;
    const size_t n = (size_t)b * HWc + hw;

    float pyv = g_py[idx], pxv = g_px[idx], m = g_mask[idx];
    float y0f = floorf(pyv), x0f = floorf(pxv);
    float wy = pyv - y0f, wx = pxv - x0f;
    int y0 = (int)y0f, x0 = (int)x0f;
    int y1 = y0 + 1, x1 = x0 + 1;
    float vy0 = (y0 >= 0 && y0 < HH) ? 1.f : 0.f;
    float vy1 = (y1 >= 0 && y1 < HH) ? 1.f : 0.f;
    float vx0 = (x0 >= 0 && x0 < WW) ? 1.f : 0.f;
    float vx1 = (x1 >= 0 && x1 < WW) ? 1.f : 0.f;
    float w00 = (1.f - wy) * (1.f - wx) * m * vy0 * vx0;
    float w01 = (1.f - wy) * wx         * m * vy0 * vx1;
    float w10 = wy         * (1.f - wx) * m * vy1 * vx0;
    float w11 = wy         * wx         * m * vy1 * vx1;

    int cy0 = min(max(y0, 0), HH - 1), cy1 = min(max(y1, 0), HH - 1);
    int cx0 = min(max(x0, 0), WW - 1), cx1 = min(max(x1, 0), WW - 1);
    int o00 = cy0 * WW + cx0, o01 = cy0 * WW + cx1;
    int o10 = cy1 * WW + cx0, o11 = cy1 * WW + cx1;

    const float* base = x + (size_t)b * C * HWc;
    size_t outBase = n * (size_t)K + (size_t)k * C;

    for (int c = 0; c < C; c += 4) {
        uint16_t h[4];
#pragma unroll
        for (int j = 0; j < 4; j++) {
            const float* p = base + (size_t)(c + j) * HWc;
            float v = w00 * p[o00] + w01 * p[o01] + w10 * p[o10] + w11 * p[o11];
            h[j] = __half_as_ushort(__float2half_rn(v));
        }
        uint2 pk;
        pk.x = (uint32_t)h[0] | ((uint32_t)h[1] << 16);
        pk.y = (uint32_t)h[2] | ((uint32_t)h[3] << 16);
        *reinterpret_cast<uint2*>(&g_col[outBase + c]) = pk;
    }
}

// ---------------- 3a) weight repack+split: wA[o][tap*C+c] = w[o][c][tap] -----
__global__ void repack_split_kernel(const float* __restrict__ w,
                                    int O, int Opad, int C)
{
    int K = 9 * C;
    int idx = blockIdx.x * blockDim.x + threadIdx.x;
    if (idx >= Opad * K) return;
    int kk = idx % K;
    int o  = idx / K;
    int tap = kk / C;
    int c   = kk % C;
    float v = (o < O) ? w[((size_t)o * C + c) * 9 + tap] : 0.f;
    __half h = __float2half_rn(v);
    __half l = __float2half_rn(v - __half2float(h));
    g_wAh[idx] = __half_as_ushort(h);
    g_wAl[idx] = __half_as_ushort(l);
}

// ---------------- 3b) fp16 A-split HMMA GEMM ---------------------------------
// D[O,N] = (Ah+Al) · col^T, 2 MMA passes.  CTA tile BMxBN (BN=128).
// BM=128: 256 thr, 8 warps (4Mx2N), warp tile 32x64.
// BM=256: 512 thr, 16 warps (4Mx4N), warp tile 64x32.
// KC=64 bf16 (128B rows), RS=144 padded stride (bank-exact ldmatrix).
#define KC 64
#define RS 144
#define GSMEM(BM) (2 * (2 * (BM) + 128) * RS)

template<int BM>
__global__ void __launch_bounds__(BM == 256 ? 512 : 256)
dcn_gemm_kernel(const float* __restrict__ bias, float* __restrict__ out,
                int K, int O)
{
    constexpr int THREADS = (BM == 256) ? 512 : 256;
    constexpr int WN = (BM == 256) ? 4 : 2;     // warps along N
    constexpr int MT = (BM == 256) ? 4 : 2;     // 16-row m-tiles per warp
    constexpr int NT = 8 / (WN / 2);            // 8-col n-tiles per warp: 4 or 8
    constexpr int STG = (2 * BM + 128) * RS;    // stage size (bytes)
    constexpr int ASZ = BM * RS;                // one A tile

    extern __shared__ char smem[];
    const uint32_t sb = smem_u32(smem);
    const int tid = threadIdx.x, lid = tid & 31, wid = tid >> 5;
    const int warpM = wid & 3;
    const int warpN = wid >> 2;
    const int m0 = blockIdx.y * BM;
    const int n0 = blockIdx.x * 128;

    float acc[MT][NT][4];
#pragma unroll
    for (int mt = 0; mt < MT; mt++)
#pragma unroll
        for (int nt = 0; nt < NT; nt++)
#pragma unroll
            for (int r = 0; r < 4; r++) acc[mt][nt][r] = 0.f;

    const char* pAh = (const char*)g_wAh + (size_t)m0 * K * 2;
    const char* pAl = (const char*)g_wAl + (size_t)m0 * K * 2;
    const char* pB  = (const char*)g_col + (size_t)n0 * K * 2;

    auto load_chunk = [&](int c, int buf) {
        size_t kb = (size_t)c * (KC * 2);
        uint32_t sbase = sb + (uint32_t)buf * STG;
        constexpr int SEGS = (2 * BM + 128) * 8;
#pragma unroll
        for (int i = 0; i < SEGS / THREADS; i++) {
            int s   = tid + i * THREADS;
            int row = s >> 3;
            int seg = s & 7;
            const char* g;
            uint32_t so;
            if (row < BM) {
                g  = pAh + (size_t)row * K * 2 + kb + (size_t)seg * 16;
                so = sbase + row * RS + seg * 16;
            } else if (row < 2 * BM) {
                int r = row - BM;
                g  = pAl + (size_t)r * K * 2 + kb + (size_t)seg * 16;
                so = sbase + ASZ + r * RS + seg * 16;
            } else {
                int r = row - 2 * BM;
                g  = pB + (size_t)r * K * 2 + kb + (size_t)seg * 16;
                so = sbase + 2 * ASZ + r * RS + seg * 16;
            }
            cp16(so, g);
        }
    };

    auto compute_chunk = [&](int buf) {
        uint32_t base = sb + (uint32_t)buf * STG;
        const uint32_t lrow = lid & 15;
        const uint32_t lcol = (lid >> 4) * 16;
#pragma unroll
        for (int ks = 0; ks < 4; ks++) {
            const uint32_t kb = ks * 32;
            uint32_t bb[NT][2];
#pragma unroll
            for (int np = 0; np < NT / 2; np++) {
                uint32_t t[4];
                uint32_t r = warpN * (8 * NT) + np * 16 + lrow;
                ldsm4(t, base + 2 * ASZ + r * RS + kb + lcol);
                bb[2 * np][0] = t[0]; bb[2 * np][1] = t[2];
                bb[2 * np + 1][0] = t[1]; bb[2 * np + 1][1] = t[3];
            }
            uint32_t af[MT][4];
#pragma unroll
            for (int mt = 0; mt < MT; mt++) {
                uint32_t r = warpM * (16 * MT) + mt * 16 + lrow;
                ldsm4(af[mt], base + r * RS + kb + lcol);
            }
#pragma unroll
            for (int mt = 0; mt < MT; mt++)
#pragma unroll
                for (int nt = 0; nt < NT; nt++)
                    mma_f16(acc[mt][nt], af[mt], bb[nt]);      // Ah*B
#pragma unroll
            for (int mt = 0; mt < MT; mt++) {
                uint32_t r = warpM * (16 * MT) + mt * 16 + lrow;
                ldsm4(af[mt], base + ASZ + r * RS + kb + lcol);
            }
#pragma unroll
            for (int mt = 0; mt < MT; mt++)
#pragma unroll
                for (int nt = 0; nt < NT; nt++)
                    mma_f16(acc[mt][nt], af[mt], bb[nt]);      // Al*B
        }
    };

    const int nCh = K / KC;
    load_chunk(0, 0);
    asm volatile("cp.async.commit_group;" ::: "memory");

    for (int c = 0; c < nCh; c++) {
        int buf = c & 1;
        if (c + 1 < nCh) {
            load_chunk(c + 1, buf ^ 1);
            asm volatile("cp.async.commit_group;" ::: "memory");
            asm volatile("cp.async.wait_group 1;" ::: "memory");
        } else {
            asm volatile("cp.async.wait_group 0;" ::: "memory");
        }
        __syncthreads();
        compute_chunk(buf);
        __syncthreads();
    }

    // ---- epilogue: +bias, scatter into [B, O, H, W] -------------------------
    const int b   = n0 / HWc;
    const int hw0 = n0 % HWc;
    const int grp = lid >> 2;
    const int tig = lid & 3;
#pragma unroll
    for (int mt = 0; mt < MT; mt++) {
        int oA = m0 + warpM * (16 * MT) + mt * 16 + grp;
        int oB = oA + 8;
#pragma unroll
        for (int nt = 0; nt < NT; nt++) {
            int cn = warpN * (8 * NT) + nt * 8 + tig * 2;
            if (oA < O) {
                float bv = bias[oA];
                float2 v = make_float2(acc[mt][nt][0] + bv, acc[mt][nt][1] + bv);
                *(float2*)(out + ((size_t)b * O + oA) * HWc + hw0 + cn) = v;
            }
            if (oB < O) {
                float bv = bias[oB];
                float2 v = make_float2(acc[mt][nt][2] + bv, acc[mt][nt][3] + bv);
                *(float2*)(out + ((size_t)b * O + oB) * HWc + hw0 + cn) = v;
            }
        }
    }
}

// ---------------- host-side layer driver -------------------------------------
static void run_layer(const float* in, int C,
                      const float* ow, const float* obias,
                      const float* w, const float* bias,
                      int O, int Opad, float* out)
{
    dim3 gOff(WW / 32, HH / 8, BB);
    offset_conv_kernel<16><<<gOff, 256>>>(in, ow, obias, C);

    int nG = BB * 9 * HWc;
    gather_kernel<<<(nG + 255) / 256, 256>>>(in, C);

    int K = 9 * C;
    int nW = Opad * K;
    repack_split_kernel<<<(nW + 255) / 256, 256>>>(w, O, Opad, C);

    if (Opad >= 256) {
        dim3 grid(NN / 128, Opad / 256);
        dcn_gemm_kernel<256><<<grid, 512, GSMEM(256)>>>(bias, out, K, O);
    } else {
        dim3 grid(NN / 128, Opad / 128);
        dcn_gemm_kernel<128><<<grid, 256, GSMEM(128)>>>(bias, out, K, O);
    }
}

extern "C" void kernel_launch(void* const* d_in, const int* in_sizes, int n_in,
                              void* d_out, int out_size)
{
    const float* x   = (const float*)d_in[0];
    const float* ow1 = (const float*)d_in[1];
    const float* ob1 = (const float*)d_in[2];
    const float* w1  = (const float*)d_in[3];
    const float* b1  = (const float*)d_in[4];
    const float* ow2 = (const float*)d_in[5];
    const float* ob2 = (const float*)d_in[6];
    const float* w2  = (const float*)d_in[7];
    const float* b2  = (const float*)d_in[8];
    const float* ow3 = (const float*)d_in[9];
    const float* ob3 = (const float*)d_in[10];
    const float* w3  = (const float*)d_in[11];
    const float* b3  = (const float*)d_in[12];
    float* out = (float*)d_out;

    cudaFuncSetAttribute(dcn_gemm_kernel<128>,
                         cudaFuncAttributeMaxDynamicSharedMemorySize, GSMEM(128));
    cudaFuncSetAttribute(dcn_gemm_kernel<256>,
                         cudaFuncAttributeMaxDynamicSharedMemorySize, GSMEM(256));

    float *y1 = nullptr, *y2 = nullptr;
    cudaGetSymbolAddress((void**)&y1, g_y1);
    cudaGetSymbolAddress((void**)&y2, g_y2);

    run_layer(x,   64, ow1, ob1, w1, b1,  64, 128, y1);
    run_layer(y1,  64, ow2, ob2, w2, b2, 512, 512, y2);
    run_layer(y2, 512, ow3, ob3, w3, b3, 256, 256, out);
}